// round 1
// baseline (speedup 1.0000x reference)
#include <cuda_runtime.h>
#include <math.h>

// Problem constants (shapes fixed by the dataset)
#define B 128
#define C 6
#define H 224
#define W 224
#define HWSZ (H*W)          // 50176
#define HW4 (HWSZ/4)        // 12544
#define POOL 7
#define NS (POOL*POOL)      // 49
#define BC (B*C)            // 768
#define CS (C*NS)           // 294
#define FEAT (3*C)          // 18

// Scratch (device globals — no allocation allowed)
__device__ float g_pooled[BC * NS];
__device__ float g_gsp[BC * NS];

// Prior matrix P[c][d] row-major and sign vector
__constant__ float c_prior[36] = {
    1.0f,  0.0f,  0.6f,  0.0f, -2.0f, 0.0f,   // row 0
    0.0f,  1.0f,  0.6f,  0.0f,  0.0f, 0.0f,   // row 1
    0.1f,  0.1f,  0.5f,  0.0f,  0.0f, 0.0f,   // row 2
    0.0f,  0.0f,  0.0f,  1.0f,  0.0f, 0.0f,   // row 3
    0.0f,  0.0f,  0.0f,  0.0f,  1.0f, 0.2f,   // row 4
    0.0f, -0.6f, -0.6f, -0.6f,  0.6f, 1.0f    // row 5
};
__constant__ float c_sign[6] = {1.f, -1.f, 1.f, -1.f, 1.f, 1.f};

// ---------------------------------------------------------------------------
// Kernel 1: per-(b,c) channel. Load 224x224 into smem (single DRAM read),
// compute mean/std(ddof=1), then sigmoid(2*(x-mean)/std) and 32x32 avg-pool
// into g_pooled[bc][49].
// ---------------------------------------------------------------------------
__global__ __launch_bounds__(1024, 1)
void gate_pool_kernel(const float* __restrict__ x)
{
    extern __shared__ float s[];           // 50176 floats = 200704 B
    __shared__ float ra[32], rb[32];
    __shared__ float s_mean, s_scale;

    const int bc = blockIdx.x;
    const float4* __restrict__ xin = (const float4*)(x + (size_t)bc * HWSZ);
    float4* s4 = (float4*)s;

    float sum = 0.f, sq = 0.f;
    for (int i = threadIdx.x; i < HW4; i += 1024) {
        float4 v = xin[i];
        s4[i] = v;
        sum += (v.x + v.y) + (v.z + v.w);
        sq  += (v.x*v.x + v.y*v.y) + (v.z*v.z + v.w*v.w);
    }

    // block reduction (32 warps)
    const int warp = threadIdx.x >> 5, lane = threadIdx.x & 31;
    #pragma unroll
    for (int o = 16; o; o >>= 1) {
        sum += __shfl_down_sync(0xffffffffu, sum, o);
        sq  += __shfl_down_sync(0xffffffffu, sq,  o);
    }
    if (lane == 0) { ra[warp] = sum; rb[warp] = sq; }
    __syncthreads();                       // also fences smem tile writes
    if (warp == 0) {
        sum = ra[lane]; sq = rb[lane];
        #pragma unroll
        for (int o = 16; o; o >>= 1) {
            sum += __shfl_down_sync(0xffffffffu, sum, o);
            sq  += __shfl_down_sync(0xffffffffu, sq,  o);
        }
        if (lane == 0) {
            const float invN = 1.0f / (float)HWSZ;
            float mean = sum * invN;
            float var = (sq - sum * sum * invN) * (1.0f / (float)(HWSZ - 1));
            var = fmaxf(var, 0.0f);
            float stdv = sqrtf(var) + 1e-5f;
            s_mean = mean;
            s_scale = 2.0f / stdv;         // /std /TAU with TAU=0.5
        }
    }
    __syncthreads();
    const float mean = s_mean, scale = s_scale;

    // pooling: warp w handles windows w, w+32 (49 windows of 32x32)
    for (int win = warp; win < NS; win += 32) {
        const int py = win / POOL, px = win - py * POOL;
        const float* base = s + (py * 32) * W + px * 32 + lane;
        float acc = 0.f;
        #pragma unroll
        for (int r = 0; r < 32; ++r) {
            float z = (base[r * W] - mean) * scale;
            acc += __fdividef(1.0f, 1.0f + __expf(-z));
        }
        #pragma unroll
        for (int o = 16; o; o >>= 1) acc += __shfl_down_sync(0xffffffffu, acc, o);
        if (lane == 0) g_pooled[bc * NS + win] = acc * (1.0f / 1024.0f);
    }
}

// ---------------------------------------------------------------------------
// Kernel 2: per-batch graph mixing (tiny). One block per b, 320 threads.
//  salient -> message = einsum(salient, P_current, Dxx) -> relu -> sign flip
//  writes gsp to g_gsp and the 18 pooled features to d_out[0 : B*18).
// ---------------------------------------------------------------------------
__global__ __launch_bounds__(320)
void graph_kernel(const float* __restrict__ P_delta, float* __restrict__ feat_out)
{
    __shared__ float xs[CS], sal[CS], gs[CS], Pc[36], smean[C];
    const int b = blockIdx.x;
    const int t = threadIdx.x;

    if (t < CS) xs[t] = g_pooled[b * CS + t];
    if (t < 36) Pc[t] = c_prior[t] + 0.2f * tanhf(P_delta[t]);
    __syncthreads();

    if (t < C) {
        float m = 0.f;
        #pragma unroll
        for (int s = 0; s < NS; ++s) m += xs[t * NS + s];
        smean[t] = m * (1.0f / (float)NS);
    }
    __syncthreads();

    if (t < CS) {
        int c = t / NS;
        sal[t] = fmaxf(c_sign[c] * (xs[t] - smean[c]), 0.0f);
    }
    __syncthreads();

    if (t < CS) {
        const int d = t / NS, tt = t - d * NS;
        const int ty = tt / POOL, tx = tt - ty * POOL;
        const float p0 = Pc[d],      p1 = Pc[6 + d],  p2 = Pc[12 + d];
        const float p3 = Pc[18 + d], p4 = Pc[24 + d], p5 = Pc[30 + d];
        float acc = 0.f;
        int s = 0;
        #pragma unroll
        for (int sy = 0; sy < POOL; ++sy) {
            const float dy = (float)(sy - ty);
            const float dy2 = dy * dy;
            #pragma unroll
            for (int sx = 0; sx < POOL; ++sx, ++s) {
                const float dx = (float)(sx - tx);
                const float w = __expf(-(dy2 + dx * dx) * 0.78125f);  // 1/(2*0.8^2)
                const float tmp = sal[s]          * p0 + sal[NS + s]   * p1
                                + sal[2*NS + s]   * p2 + sal[3*NS + s] * p3
                                + sal[4*NS + s]   * p4 + sal[5*NS + s] * p5;
                acc += w * tmp;
            }
        }
        const float gv = c_sign[d] * fmaxf(acc, 0.0f);
        gs[t] = gv;
        g_gsp[b * CS + t] = gv;
    }
    __syncthreads();

    if (t < C) {
        float m = 0.f, mx = -3.402823466e38f, mn = 3.402823466e38f;
        #pragma unroll
        for (int s = 0; s < NS; ++s) {
            float v = gs[t * NS + s];
            m += v; mx = fmaxf(mx, v); mn = fminf(mn, v);
        }
        feat_out[b * FEAT + t]         = m * (1.0f / (float)NS);
        feat_out[b * FEAT + C + t]     = mx;
        feat_out[b * FEAT + 2 * C + t] = mn;
    }
}

// ---------------------------------------------------------------------------
// Kernel 3: bilinear upsample 7x7 -> 224x224, half-pixel centers, edge clamp.
// One block per (b,c); float4 stores.
// ---------------------------------------------------------------------------
__global__ __launch_bounds__(512)
void upsample_kernel(float* __restrict__ out)
{
    __shared__ float g[NS];
    const int bc = blockIdx.x;
    if (threadIdx.x < NS) g[threadIdx.x] = g_gsp[bc * NS + threadIdx.x];
    __syncthreads();

    float4* __restrict__ o = (float4*)(out + (size_t)bc * HWSZ);
    for (int i = threadIdx.x; i < HW4; i += 512) {
        const int row = i / 56;                 // 224/4 float4 per row
        const int j0 = (i - row * 56) * 4;
        const float sy = (row + 0.5f) * (1.0f / 32.0f) - 0.5f;
        const float y0f = floorf(sy);
        const float fy = sy - y0f;
        const int y0 = max(0, min(6, (int)y0f));
        const int y1 = max(0, min(6, (int)y0f + 1));
        const float* gr0 = g + y0 * POOL;
        const float* gr1 = g + y1 * POOL;

        float4 r;
        float* pr = &r.x;
        #pragma unroll
        for (int k = 0; k < 4; ++k) {
            const int j = j0 + k;
            const float sx = (j + 0.5f) * (1.0f / 32.0f) - 0.5f;
            const float x0f = floorf(sx);
            const float fx = sx - x0f;
            const int x0 = max(0, min(6, (int)x0f));
            const int x1 = max(0, min(6, (int)x0f + 1));
            const float top = gr0[x0] + fx * (gr0[x1] - gr0[x0]);
            const float bot = gr1[x0] + fx * (gr1[x1] - gr1[x0]);
            pr[k] = top + fy * (bot - top);
        }
        o[i] = r;
    }
}

// ---------------------------------------------------------------------------
extern "C" void kernel_launch(void* const* d_in, const int* in_sizes, int n_in,
                              void* d_out, int out_size)
{
    const float* x       = (const float*)d_in[0];   // (128,6,224,224) f32
    const float* P_delta = (const float*)d_in[1];   // (6,6) f32
    float* out = (float*)d_out;                     // [B*18 features | B*C*H*W upsampled]

    static const size_t SMEM1 = HWSZ * sizeof(float);   // 200704 B
    cudaFuncSetAttribute(gate_pool_kernel,
                         cudaFuncAttributeMaxDynamicSharedMemorySize, (int)SMEM1);

    gate_pool_kernel<<<BC, 1024, SMEM1>>>(x);
    graph_kernel<<<B, 320>>>(P_delta, out);
    upsample_kernel<<<BC, 512>>>(out + (size_t)B * FEAT);
}

// round 3
// speedup vs baseline: 1.3069x; 1.3069x over previous
#include <cuda_runtime.h>
#include <math.h>

#define B 128
#define C 6
#define H 224
#define W 224
#define HWSZ (H*W)          // 50176
#define HW4 (HWSZ/4)        // 12544
#define POOL 7
#define NS (POOL*POOL)      // 49
#define BC (B*C)            // 768
#define CS (C*NS)           // 294
#define FEAT (3*C)          // 18

// Scratch (device globals — no allocation allowed)
__device__ float g_pooled[BC * NS];
__device__ float g_gsp[BC * NS];

// Prior matrix P[c][d] row-major and sign vector
__constant__ float c_prior[36] = {
    1.0f,  0.0f,  0.6f,  0.0f, -2.0f, 0.0f,
    0.0f,  1.0f,  0.6f,  0.0f,  0.0f, 0.0f,
    0.1f,  0.1f,  0.5f,  0.0f,  0.0f, 0.0f,
    0.0f,  0.0f,  0.0f,  1.0f,  0.0f, 0.0f,
    0.0f,  0.0f,  0.0f,  0.0f,  1.0f, 0.2f,
    0.0f, -0.6f, -0.6f, -0.6f,  0.6f, 1.0f
};
__constant__ float c_sign[6] = {1.f, -1.f, 1.f, -1.f, 1.f, 1.f};

// ---------------------------------------------------------------------------
// Kernel 1: per-(b,c) channel, two-pass over L2 (no big smem tile).
//   pass 1: stream channel from DRAM, accumulate sum / sumsq.
//   pass 2: re-read channel (L2 hit: ~3 resident blocks/SM x 200KB = 89MB),
//           sigmoid gate + 32x32 avg-pool into g_pooled.
// ---------------------------------------------------------------------------
__global__ __launch_bounds__(512, 3)
void gate_pool_kernel(const float* __restrict__ x)
{
    __shared__ float ra[16], rb[16];
    __shared__ float s_mean, s_scale;

    const int bc = blockIdx.x;
    const float* __restrict__ xc = x + (size_t)bc * HWSZ;
    const float4* __restrict__ xin = (const float4*)xc;

    // ---- pass 1: stats ----
    float sum = 0.f, sq = 0.f;
    #pragma unroll 4
    for (int i = threadIdx.x; i < HW4; i += 512) {
        float4 v = xin[i];
        sum += (v.x + v.y) + (v.z + v.w);
        sq  += (v.x*v.x + v.y*v.y) + (v.z*v.z + v.w*v.w);
    }

    const int warp = threadIdx.x >> 5, lane = threadIdx.x & 31;
    #pragma unroll
    for (int o = 16; o; o >>= 1) {
        sum += __shfl_down_sync(0xffffffffu, sum, o);
        sq  += __shfl_down_sync(0xffffffffu, sq,  o);
    }
    if (lane == 0) { ra[warp] = sum; rb[warp] = sq; }
    __syncthreads();
    if (warp == 0) {
        sum = (lane < 16) ? ra[lane] : 0.f;
        sq  = (lane < 16) ? rb[lane] : 0.f;
        #pragma unroll
        for (int o = 8; o; o >>= 1) {
            sum += __shfl_down_sync(0xffffffffu, sum, o);
            sq  += __shfl_down_sync(0xffffffffu, sq,  o);
        }
        if (lane == 0) {
            const float invN = 1.0f / (float)HWSZ;
            float mean = sum * invN;
            float var = (sq - sum * sum * invN) * (1.0f / (float)(HWSZ - 1));
            var = fmaxf(var, 0.0f);
            s_mean = mean;
            s_scale = 2.0f / (sqrtf(var) + 1e-5f);   // /std /TAU, TAU=0.5
        }
    }
    __syncthreads();
    const float mean = s_mean, scale = s_scale;

    // ---- pass 2: gate + pool (reads hit L2) ----
    for (int win = warp; win < NS; win += 16) {
        const int py = win / POOL, px = win - py * POOL;
        const float4* __restrict__ base =
            (const float4*)(xc + (py * 32 + lane) * W + px * 32);
        float acc = 0.f;
        #pragma unroll
        for (int k = 0; k < 8; ++k) {
            float4 v = base[k];
            float z0 = (v.x - mean) * scale;
            float z1 = (v.y - mean) * scale;
            float z2 = (v.z - mean) * scale;
            float z3 = (v.w - mean) * scale;
            acc += __fdividef(1.0f, 1.0f + __expf(-z0));
            acc += __fdividef(1.0f, 1.0f + __expf(-z1));
            acc += __fdividef(1.0f, 1.0f + __expf(-z2));
            acc += __fdividef(1.0f, 1.0f + __expf(-z3));
        }
        #pragma unroll
        for (int o = 16; o; o >>= 1) acc += __shfl_down_sync(0xffffffffu, acc, o);
        if (lane == 0) g_pooled[bc * NS + win] = acc * (1.0f / 1024.0f);
    }
}

// ---------------------------------------------------------------------------
// Kernel 2: per-batch graph mixing (tiny). One block per b, 320 threads.
// ---------------------------------------------------------------------------
__global__ __launch_bounds__(320)
void graph_kernel(const float* __restrict__ P_delta, float* __restrict__ feat_out)
{
    __shared__ float xs[CS], sal[CS], gs[CS], Pc[36], smean[C];
    const int b = blockIdx.x;
    const int t = threadIdx.x;

    if (t < CS) xs[t] = g_pooled[b * CS + t];
    if (t < 36) Pc[t] = c_prior[t] + 0.2f * tanhf(P_delta[t]);
    __syncthreads();

    if (t < C) {
        float m = 0.f;
        #pragma unroll
        for (int s = 0; s < NS; ++s) m += xs[t * NS + s];
        smean[t] = m * (1.0f / (float)NS);
    }
    __syncthreads();

    if (t < CS) {
        int c = t / NS;
        sal[t] = fmaxf(c_sign[c] * (xs[t] - smean[c]), 0.0f);
    }
    __syncthreads();

    if (t < CS) {
        const int d = t / NS, tt = t - d * NS;
        const int ty = tt / POOL, tx = tt - ty * POOL;
        const float p0 = Pc[d],      p1 = Pc[6 + d],  p2 = Pc[12 + d];
        const float p3 = Pc[18 + d], p4 = Pc[24 + d], p5 = Pc[30 + d];
        float acc = 0.f;
        int s = 0;
        #pragma unroll
        for (int sy = 0; sy < POOL; ++sy) {
            const float dy = (float)(sy - ty);
            const float dy2 = dy * dy;
            #pragma unroll
            for (int sx = 0; sx < POOL; ++sx, ++s) {
                const float dx = (float)(sx - tx);
                const float w = __expf(-(dy2 + dx * dx) * 0.78125f);
                const float tmp = sal[s]        * p0 + sal[NS + s]   * p1
                                + sal[2*NS + s] * p2 + sal[3*NS + s] * p3
                                + sal[4*NS + s] * p4 + sal[5*NS + s] * p5;
                acc += w * tmp;
            }
        }
        const float gv = c_sign[d] * fmaxf(acc, 0.0f);
        gs[t] = gv;
        g_gsp[b * CS + t] = gv;
    }
    __syncthreads();

    if (t < C) {
        float m = 0.f, mx = -3.402823466e38f, mn = 3.402823466e38f;
        #pragma unroll
        for (int s = 0; s < NS; ++s) {
            float v = gs[t * NS + s];
            m += v; mx = fmaxf(mx, v); mn = fminf(mn, v);
        }
        feat_out[b * FEAT + t]         = m * (1.0f / (float)NS);
        feat_out[b * FEAT + C + t]     = mx;
        feat_out[b * FEAT + 2 * C + t] = mn;
    }
}

// ---------------------------------------------------------------------------
// Kernel 3: bilinear upsample 7x7 -> 224x224 via precomputed tables.
//   hrows[7][224] (16B-aligned!): horizontal interpolation of each source row
//   ytab: per-output-row y0/y1/fy
// Hot loop per float4: 2x LDS.128 + 4 FMA + 1 STG.128 -> store-BW bound.
// ---------------------------------------------------------------------------
__global__ __launch_bounds__(256)
void upsample_kernel(float* __restrict__ out)
{
    __shared__ __align__(16) float hrows[POOL][W];   // 6272 B, 16B-aligned rows
    __shared__ __align__(16) float g[NS + 3];
    __shared__ float fyv[H];
    __shared__ int   y0i[H], y1i[H];

    const int bc = blockIdx.x;
    const int t = threadIdx.x;
    if (t < NS) g[t] = g_gsp[bc * NS + t];
    __syncthreads();

    for (int i = t; i < POOL * W; i += 256) {
        const int r = i / W, j = i - r * W;
        const float sx = (j + 0.5f) * (1.0f / 32.0f) - 0.5f;
        const float x0f = floorf(sx);
        const float fx = sx - x0f;
        const int x0 = max(0, min(6, (int)x0f));
        const int x1 = max(0, min(6, (int)x0f + 1));
        const float a = g[r * POOL + x0];
        hrows[r][j] = a + fx * (g[r * POOL + x1] - a);
    }
    for (int j = t; j < H; j += 256) {
        const float sy = (j + 0.5f) * (1.0f / 32.0f) - 0.5f;
        const float y0f = floorf(sy);
        fyv[j] = sy - y0f;
        y0i[j] = max(0, min(6, (int)y0f));
        y1i[j] = max(0, min(6, (int)y0f + 1));
    }
    __syncthreads();

    float4* __restrict__ o = (float4*)(out + (size_t)bc * HWSZ);
    #pragma unroll 4
    for (int i = t; i < HW4; i += 256) {
        const int row = i / 56;             // 56 float4 per output row
        const int c4  = i - row * 56;
        const float fy = fyv[row];
        const float4 a  = ((const float4*)hrows[y0i[row]])[c4];
        const float4 bv = ((const float4*)hrows[y1i[row]])[c4];
        float4 r;
        r.x = a.x + fy * (bv.x - a.x);
        r.y = a.y + fy * (bv.y - a.y);
        r.z = a.z + fy * (bv.z - a.z);
        r.w = a.w + fy * (bv.w - a.w);
        __stcs(&o[i], r);                   // streaming store: evict-first
    }
}

// ---------------------------------------------------------------------------
extern "C" void kernel_launch(void* const* d_in, const int* in_sizes, int n_in,
                              void* d_out, int out_size)
{
    const float* x       = (const float*)d_in[0];   // (128,6,224,224) f32
    const float* P_delta = (const float*)d_in[1];   // (6,6) f32
    float* out = (float*)d_out;                     // [B*18 | B*C*H*W]

    gate_pool_kernel<<<BC, 512>>>(x);
    graph_kernel<<<B, 320>>>(P_delta, out);
    upsample_kernel<<<BC, 256>>>(out + (size_t)B * FEAT);
}

// round 4
// speedup vs baseline: 1.6585x; 1.2691x over previous
#include <cuda_runtime.h>
#include <math.h>

#define B 128
#define C 6
#define H 224
#define W 224
#define HWSZ (H*W)          // 50176
#define HW4 (HWSZ/4)        // 12544
#define POOL 7
#define NS (POOL*POOL)      // 49
#define BC (B*C)            // 768
#define CS (C*NS)           // 294
#define FEAT (3*C)          // 18

__device__ float g_pooled[BC * NS];

__constant__ float c_prior[36] = {
    1.0f,  0.0f,  0.6f,  0.0f, -2.0f, 0.0f,
    0.0f,  1.0f,  0.6f,  0.0f,  0.0f, 0.0f,
    0.1f,  0.1f,  0.5f,  0.0f,  0.0f, 0.0f,
    0.0f,  0.0f,  0.0f,  1.0f,  0.0f, 0.0f,
    0.0f,  0.0f,  0.0f,  0.0f,  1.0f, 0.2f,
    0.0f, -0.6f, -0.6f, -0.6f,  0.6f, 1.0f
};
__constant__ float c_sign[6] = {1.f, -1.f, 1.f, -1.f, 1.f, 1.f};

__device__ __forceinline__ float tanh_fast(float x) {
    float y;
    asm("tanh.approx.f32 %0, %1;" : "=f"(y) : "f"(x));
    return y;
}

// ---------------------------------------------------------------------------
// Kernel 1: per-(b,c) channel, two-pass over L2.
//   pass 1: stream channel from DRAM -> sum / sumsq.
//   pass 2: re-read (L2-resident), gate via 1-MUFU tanh, 32x32 avg-pool.
//   sigmoid mean over window = 0.5 + (1/2048) * sum(tanh((x-mean)/std))
// ---------------------------------------------------------------------------
__global__ __launch_bounds__(512, 3)
void gate_pool_kernel(const float* __restrict__ x)
{
    __shared__ float ra[16], rb[16];
    __shared__ float s_inv, s_ofs;

    const int bc = blockIdx.x;
    const float* __restrict__ xc = x + (size_t)bc * HWSZ;
    const float4* __restrict__ xin = (const float4*)xc;

    // ---- pass 1: stats ----
    float sum = 0.f, sq = 0.f;
    #pragma unroll 4
    for (int i = threadIdx.x; i < HW4; i += 512) {
        float4 v = xin[i];
        sum += (v.x + v.y) + (v.z + v.w);
        sq  += (v.x*v.x + v.y*v.y) + (v.z*v.z + v.w*v.w);
    }

    const int warp = threadIdx.x >> 5, lane = threadIdx.x & 31;
    #pragma unroll
    for (int o = 16; o; o >>= 1) {
        sum += __shfl_down_sync(0xffffffffu, sum, o);
        sq  += __shfl_down_sync(0xffffffffu, sq,  o);
    }
    if (lane == 0) { ra[warp] = sum; rb[warp] = sq; }
    __syncthreads();
    if (warp == 0) {
        sum = (lane < 16) ? ra[lane] : 0.f;
        sq  = (lane < 16) ? rb[lane] : 0.f;
        #pragma unroll
        for (int o = 8; o; o >>= 1) {
            sum += __shfl_down_sync(0xffffffffu, sum, o);
            sq  += __shfl_down_sync(0xffffffffu, sq,  o);
        }
        if (lane == 0) {
            const float invN = 1.0f / (float)HWSZ;
            float mean = sum * invN;
            float var = (sq - sum * sum * invN) * (1.0f / (float)(HWSZ - 1));
            var = fmaxf(var, 0.0f);
            float inv_std = 1.0f / (sqrtf(var) + 1e-5f);   // tanh arg = z/2 = (x-mean)/std
            s_inv = inv_std;
            s_ofs = -mean * inv_std;
        }
    }
    __syncthreads();
    const float s2 = s_inv, o2 = s_ofs;

    // ---- pass 2: gate + pool (coalesced: lane = 4-row group x 8 float4) ----
    const int sub = lane >> 3;      // 0..3  row within 4-row group
    const int c4  = lane & 7;       // 0..7  float4 within 128B row chunk
    for (int win = warp; win < NS; win += 16) {
        const int py = win / POOL, px = win - py * POOL;
        const float4* __restrict__ base =
            (const float4*)(xc + (py * 32 + sub) * W + px * 32) + c4;
        float acc = 0.f;
        #pragma unroll
        for (int r = 0; r < 8; ++r) {          // rows sub, sub+4, ..., sub+28
            float4 v = base[r * W];            // W float4s = 4 rows
            acc += tanh_fast(fmaf(v.x, s2, o2));
            acc += tanh_fast(fmaf(v.y, s2, o2));
            acc += tanh_fast(fmaf(v.z, s2, o2));
            acc += tanh_fast(fmaf(v.w, s2, o2));
        }
        #pragma unroll
        for (int o = 16; o; o >>= 1) acc += __shfl_down_sync(0xffffffffu, acc, o);
        if (lane == 0) g_pooled[bc * NS + win] = acc * (1.0f / 2048.0f) + 0.5f;
    }
}

// ---------------------------------------------------------------------------
// Kernel 2 (fused): per-(b,c) graph mixing + feature pooling + bilinear
// upsample 7x7 -> 224x224. Each block recomputes the tiny mixing for its
// own channel (6x redundant, ~15K FMA — negligible), writes 3 feature
// scalars, then does the table-driven upsample.
// ---------------------------------------------------------------------------
__global__ __launch_bounds__(256)
void graph_upsample_kernel(const float* __restrict__ P_delta,
                           float* __restrict__ feat_out,
                           float* __restrict__ out)
{
    __shared__ float xs[CS], sal[CS], tmp[NS];
    __shared__ float Pcol[C], smean[C];
    __shared__ __align__(16) float g[52];
    __shared__ __align__(16) float hrows[POOL][W];
    __shared__ float fyv[H];
    __shared__ int   y0i[H], y1i[H];

    const int bc = blockIdx.x;
    const int b = bc / C, d = bc - b * C;     // batch, concept channel
    const int t = threadIdx.x;

    // load this batch's pooled activations (294 floats, L2 hit)
    for (int i = t; i < CS; i += 256) xs[i] = g_pooled[b * CS + i];
    if (t < C) Pcol[t] = c_prior[t * 6 + d] + 0.2f * tanhf(P_delta[t * 6 + d]);
    __syncthreads();

    if (t < C) {
        float m = 0.f;
        #pragma unroll
        for (int s = 0; s < NS; ++s) m += xs[t * NS + s];
        smean[t] = m * (1.0f / (float)NS);
    }
    __syncthreads();

    for (int i = t; i < CS; i += 256) {
        const int cc = i / NS;
        sal[i] = fmaxf(c_sign[cc] * (xs[i] - smean[cc]), 0.0f);
    }
    __syncthreads();

    if (t < NS) {   // concept contraction: tmp[s] = sum_c sal[c,s] * P[c,d]
        tmp[t] = sal[t]        * Pcol[0] + sal[NS + t]   * Pcol[1]
               + sal[2*NS + t] * Pcol[2] + sal[3*NS + t] * Pcol[3]
               + sal[4*NS + t] * Pcol[4] + sal[5*NS + t] * Pcol[5];
    }
    __syncthreads();

    if (t < NS) {   // spatial contraction: g[t] = sign * relu(sum_s w(s,t) tmp[s])
        const int ty = t / POOL, tx = t - ty * POOL;
        float acc = 0.f;
        int s = 0;
        #pragma unroll
        for (int sy = 0; sy < POOL; ++sy) {
            const float dy2 = (float)((sy - ty) * (sy - ty));
            #pragma unroll
            for (int sx = 0; sx < POOL; ++sx, ++s) {
                const float dx = (float)(sx - tx);
                acc += __expf(-(dy2 + dx * dx) * 0.78125f) * tmp[s];
            }
        }
        g[t] = c_sign[d] * fmaxf(acc, 0.0f);
    }
    __syncthreads();

    // features: mean/max/min over the 49 gsp values of this channel (warp 0)
    if (t < 32) {
        float a  = g[t];
        bool hi  = (t + 32) < NS;
        float b2 = hi ? g[t + 32] : 0.f;
        float s  = a + b2;
        float mx = hi ? fmaxf(a, b2) : a;
        float mn = hi ? fminf(a, b2) : a;
        #pragma unroll
        for (int o = 16; o; o >>= 1) {
            s  += __shfl_down_sync(0xffffffffu, s,  o);
            mx  = fmaxf(mx, __shfl_down_sync(0xffffffffu, mx, o));
            mn  = fminf(mn, __shfl_down_sync(0xffffffffu, mn, o));
        }
        if (t == 0) {
            feat_out[b * FEAT + d]         = s * (1.0f / (float)NS);
            feat_out[b * FEAT + C + d]     = mx;
            feat_out[b * FEAT + 2 * C + d] = mn;
        }
    }

    // interpolation tables (depend only on g)
    for (int i = t; i < POOL * W; i += 256) {
        const int r = i / W, j = i - r * W;
        const float sx = (j + 0.5f) * (1.0f / 32.0f) - 0.5f;
        const float x0f = floorf(sx);
        const float fx = sx - x0f;
        const int x0 = max(0, min(6, (int)x0f));
        const int x1 = max(0, min(6, (int)x0f + 1));
        const float a = g[r * POOL + x0];
        hrows[r][j] = a + fx * (g[r * POOL + x1] - a);
    }
    for (int j = t; j < H; j += 256) {
        const float sy = (j + 0.5f) * (1.0f / 32.0f) - 0.5f;
        const float y0f = floorf(sy);
        fyv[j] = sy - y0f;
        y0i[j] = max(0, min(6, (int)y0f));
        y1i[j] = max(0, min(6, (int)y0f + 1));
    }
    __syncthreads();

    float4* __restrict__ o = (float4*)(out + (size_t)bc * HWSZ);
    #pragma unroll 4
    for (int i = t; i < HW4; i += 256) {
        const int row = i / 56;
        const int cc4 = i - row * 56;
        const float fy = fyv[row];
        const float4 a  = ((const float4*)hrows[y0i[row]])[cc4];
        const float4 bv = ((const float4*)hrows[y1i[row]])[cc4];
        float4 r;
        r.x = a.x + fy * (bv.x - a.x);
        r.y = a.y + fy * (bv.y - a.y);
        r.z = a.z + fy * (bv.z - a.z);
        r.w = a.w + fy * (bv.w - a.w);
        __stcs(&o[i], r);
    }
}

// ---------------------------------------------------------------------------
extern "C" void kernel_launch(void* const* d_in, const int* in_sizes, int n_in,
                              void* d_out, int out_size)
{
    const float* x       = (const float*)d_in[0];   // (128,6,224,224) f32
    const float* P_delta = (const float*)d_in[1];   // (6,6) f32
    float* out = (float*)d_out;                     // [B*18 | B*C*H*W]

    gate_pool_kernel<<<BC, 512>>>(x);
    graph_upsample_kernel<<<BC, 256>>>(P_delta, out, out + (size_t)B * FEAT);
}